// round 5
// baseline (speedup 1.0000x reference)
#include <cuda_runtime.h>
#include <cuda_bf16.h>
#include <cstdint>

#define HW   256
#define HW2  65536
#define MAX_BS 128
#define BPB  64            // blocks per batch (256 thr * 4 px = 1024 px/block)

// Scratch (__device__ globals, zero at module load — no allocations).
// g_table is re-zeroed by gather_kernel every call (read-then-clear).
__device__ int      g_table[MAX_BS * HW2];        // two-tier winner keys
__device__ unsigned g_bits[MAX_BS * (HW2 / 32)];  // seg>0.5 bitmask
__device__ int      g_flag[MAX_BS];               // 1 if any valid px (idempotent store)
__device__ int      g_mmax[MAX_BS];               // (max masked p)+1, 0=none (idempotent max)

// ---------------------------------------------------------------------------
// K1: single-pass scatter. key = (valid?0x10000:0)|p at the REAL grid cell.
//     Also emits seg bitmask, per-batch any-valid flag, per-batch masked-max.
// ---------------------------------------------------------------------------
__global__ void __launch_bounds__(256)
scatter_kernel(const float* __restrict__ grid, const float* __restrict__ seg) {
    int blk = blockIdx.x;
    int b   = blk >> 6;                    // /BPB
    int sub = blk & (BPB - 1);
    int tid = threadIdx.x;
    int p   = (sub << 10) + (tid << 2);    // in-batch pixel index (4/thread)

    const float* segb = seg + (size_t)b * HW2;
    float4 s4 = __ldcs(reinterpret_cast<const float4*>(segb + p));
    bool v[4] = {s4.x > 0.5f, s4.y > 0.5f, s4.z > 0.5f, s4.w > 0.5f};

    // build bitmask word (32 px = 8 threads * 4 bits)
    unsigned nib = (unsigned)v[0] | ((unsigned)v[1] << 1) |
                   ((unsigned)v[2] << 2) | ((unsigned)v[3] << 3);
    unsigned w = nib << ((tid & 7) << 2);
    w |= __shfl_xor_sync(0xffffffffu, w, 1);
    w |= __shfl_xor_sync(0xffffffffu, w, 2);
    w |= __shfl_xor_sync(0xffffffffu, w, 4);
    if ((tid & 7) == 0) g_bits[(b << 11) + (p >> 5)] = w;

    const float* gxb = grid + (size_t)b * 2 * HW2;
    float4 gx4 = __ldcs(reinterpret_cast<const float4*>(gxb + p));
    float4 gy4 = __ldcs(reinterpret_cast<const float4*>(gxb + HW2 + p));
    float gx[4] = {gx4.x, gx4.y, gx4.z, gx4.w};
    float gy[4] = {gy4.x, gy4.y, gy4.z, gy4.w};

    int* tb = g_table + b * HW2;
    int mm = -1, anyv = 0;
    #pragma unroll
    for (int k = 0; k < 4; k++) {
        int ix = (int)((gx[k] + 1.0f) * 0.5f * (float)HW);
        int iy = (int)((gy[k] + 1.0f) * 0.5f * (float)HW);
        ix = min(max(ix, 0), HW - 1);
        iy = min(max(iy, 0), HW - 1);
        int key = (v[k] ? 0x10000 : 0) | (p + k);
        atomicMax(&tb[iy * HW + ix], key);       // RED.MAX (no return)
        if (v[k]) anyv = 1; else mm = p + k;     // ascending -> max masked
    }

    // warp-level reduce; lane 0 commits (sync-free, idempotent)
    anyv = __any_sync(0xffffffffu, anyv);
    #pragma unroll
    for (int o = 16; o; o >>= 1) mm = max(mm, __shfl_xor_sync(0xffffffffu, mm, o));
    if ((tid & 31) == 0) {
        if (anyv) g_flag[b] = 1;
        if (mm >= 0) atomicMax(&g_mmax[b], mm + 1);
    }
}

// ---------------------------------------------------------------------------
// K1.5: plant masked-pixel winner at (128,128) for NON-EMPTY batches only.
// ---------------------------------------------------------------------------
__global__ void plant_kernel(int bs) {
    int b = threadIdx.x;
    if (b < bs && g_flag[b] != 0) {
        int mm = g_mmax[b];
        if (mm > 0)
            atomicMax(&g_table[b * HW2 + 128 * HW + 128], 0x10000 | (mm - 1));
    }
}

// ---------------------------------------------------------------------------
// K2: decode winners + nearest-sample + write 5 output planes, and re-zero
//     the table for the next call. ix = w&~1, iy = h&~1 (half-even collapse).
// ---------------------------------------------------------------------------
__global__ void __launch_bounds__(256)
gather_kernel(const float* __restrict__ conf, const float* __restrict__ depth,
              float* __restrict__ out, int bs) {
    int blk = blockIdx.x;
    int b   = blk >> 6;
    int sub = blk & (BPB - 1);
    int tid = threadIdx.x;
    int p   = (sub << 10) + (tid << 2);

    bool emp = (__ldg(&g_flag[b]) == 0);
    int4* tp = reinterpret_cast<int4*>(g_table + b * HW2 + p);
    int4 k4 = *tp;
    *tp = make_int4(0, 0, 0, 0);           // restore zero state for next call
    int key[4] = {k4.x, k4.y, k4.z, k4.w};

    const float* db = depth + (size_t)b * HW2;
    const float* cb = conf  + (size_t)b * HW2;
    const unsigned* bb = g_bits + (b << 11);

    float4 ox, oy, od, oc, om;
    float *oxp = &ox.x, *oyp = &oy.x, *odp = &od.x, *ocp = &oc.x, *omp = &om.x;
    #pragma unroll
    for (int k = 0; k < 4; k++) {
        int s = emp ? key[k] : ((key[k] >= 0x10000) ? (key[k] & 0xFFFF) : 0);
        int ix = (s & (HW - 1)) & ~1;
        int iy = ((s >> 8) & (HW - 1)) & ~1;
        int cell = iy * HW + ix;
        float m = (emp || ((__ldg(&bb[cell >> 5]) >> (cell & 31)) & 1u)) ? 1.0f : 0.0f;
        float d = __ldg(db + cell);
        float c = __ldg(cb + cell);
        oxp[k] = ((float)ix * (1.0f / 280.0f)) * m;
        oyp[k] = ((float)iy * (1.0f / 280.0f)) * m;
        odp[k] = d * m;
        ocp[k] = c;
        omp[k] = m;
    }

    size_t o0 = (size_t)b * 3 * HW2 + p;
    __stcs(reinterpret_cast<float4*>(out + o0),           ox);
    __stcs(reinterpret_cast<float4*>(out + o0 + HW2),     oy);
    __stcs(reinterpret_cast<float4*>(out + o0 + 2 * HW2), od);
    __stcs(reinterpret_cast<float4*>(out + (size_t)bs * 3 * HW2 + (size_t)b * HW2 + p), oc);
    __stcs(reinterpret_cast<float4*>(out + (size_t)bs * 4 * HW2 + (size_t)b * HW2 + p), om);
}

// ---------------------------------------------------------------------------
extern "C" void kernel_launch(void* const* d_in, const int* in_sizes, int n_in,
                              void* d_out, int out_size) {
    const float* grid  = (const float*)d_in[0];
    const float* seg   = (const float*)d_in[1];
    const float* conf  = (const float*)d_in[2];
    const float* depth = (const float*)d_in[3];
    float* out = (float*)d_out;

    int bs = in_sizes[1] / HW2;   // 128

    scatter_kernel<<<bs * BPB, 256>>>(grid, seg);
    plant_kernel<<<1, MAX_BS>>>(bs);
    gather_kernel<<<bs * BPB, 256>>>(conf, depth, out, bs);
}

// round 6
// speedup vs baseline: 1.5842x; 1.5842x over previous
#include <cuda_runtime.h>
#include <cuda_bf16.h>
#include <cstdint>

#define HW   256
#define HW2  65536
#define MAX_BS 128
#define BPB  64            // blocks per batch (256 thr * 4 px = 1024 px/block)

// Scratch (__device__ globals, zero at module load — no allocations).
// g_table is restored to all-zero by gather_kernel (read-then-clear), so no
// memset is ever needed; g_flag/g_mmax writes are idempotent across replays.
__device__ int      g_table[MAX_BS * HW2];        // winner p per cell, 0 = empty (aliases p=0, same decode)
__device__ unsigned g_bits[MAX_BS * (HW2 / 32)];  // seg>0.5 bitmask
__device__ int      g_flag[MAX_BS];               // 1 if any valid px
__device__ int      g_mmax[MAX_BS];               // (max INVALID p)+1, 0 = none

// ---------------------------------------------------------------------------
// K1: seg pass -> bitmask + per-batch any-valid flag + max invalid index.
// ---------------------------------------------------------------------------
__global__ void __launch_bounds__(256)
count_kernel(const float* __restrict__ seg) {
    int blk = blockIdx.x;
    int b   = blk >> 6;
    int sub = blk & (BPB - 1);
    int tid = threadIdx.x;
    int p   = (sub << 10) + (tid << 2);

    const float* segb = seg + (size_t)b * HW2;
    float4 s4 = __ldcs(reinterpret_cast<const float4*>(segb + p));
    bool v[4] = {s4.x > 0.5f, s4.y > 0.5f, s4.z > 0.5f, s4.w > 0.5f};

    unsigned nib = (unsigned)v[0] | ((unsigned)v[1] << 1) |
                   ((unsigned)v[2] << 2) | ((unsigned)v[3] << 3);
    unsigned w = nib << ((tid & 7) << 2);
    w |= __shfl_xor_sync(0xffffffffu, w, 1);
    w |= __shfl_xor_sync(0xffffffffu, w, 2);
    w |= __shfl_xor_sync(0xffffffffu, w, 4);
    if ((tid & 7) == 0) g_bits[(b << 11) + (p >> 5)] = w;

    int mm = -1, anyv = 0;
    #pragma unroll
    for (int k = 0; k < 4; k++) {
        if (v[k]) anyv = 1; else mm = p + k;   // ascending -> max invalid
    }
    anyv = __any_sync(0xffffffffu, anyv);
    #pragma unroll
    for (int o = 16; o; o >>= 1) mm = max(mm, __shfl_xor_sync(0xffffffffu, mm, o));
    if ((tid & 31) == 0) {
        if (anyv) g_flag[b] = 1;               // idempotent
        if (mm >= 0) atomicMax(&g_mmax[b], mm + 1);
    }
}

// ---------------------------------------------------------------------------
// K2: scatter. Atomics ONLY for valid pixels (or all, if batch empty).
//     Invalid pixels of a non-empty batch all map to (128,128): deduped to
//     one planted atomic per batch using g_mmax.
// ---------------------------------------------------------------------------
__global__ void __launch_bounds__(256)
scatter_kernel(const float* __restrict__ grid) {
    int blk = blockIdx.x;
    int b   = blk >> 6;
    int sub = blk & (BPB - 1);
    int tid = threadIdx.x;
    int p   = (sub << 10) + (tid << 2);

    bool emp = (__ldg(&g_flag[b]) == 0);
    unsigned word = __ldg(&g_bits[(b << 11) + (p >> 5)]);

    const float* gxb = grid + (size_t)b * 2 * HW2;
    float4 gx4 = __ldcs(reinterpret_cast<const float4*>(gxb + p));
    float4 gy4 = __ldcs(reinterpret_cast<const float4*>(gxb + HW2 + p));
    float gx[4] = {gx4.x, gx4.y, gx4.z, gx4.w};
    float gy[4] = {gy4.x, gy4.y, gy4.z, gy4.w};

    int* tb = g_table + b * HW2;
    #pragma unroll
    for (int k = 0; k < 4; k++) {
        if (emp || ((word >> ((p + k) & 31)) & 1u)) {
            int ix = (int)((gx[k] + 1.0f) * 0.5f * (float)HW);
            int iy = (int)((gy[k] + 1.0f) * 0.5f * (float)HW);
            ix = min(max(ix, 0), HW - 1);
            iy = min(max(iy, 0), HW - 1);
            atomicMax(&tb[iy * HW + ix], p + k);   // RED.MAX, no return
        }
    }

    // plant masked-pixel winner once per non-empty batch
    if (sub == 0 && tid == 0 && !emp) {
        int mm = __ldg(&g_mmax[b]);
        if (mm > 0) atomicMax(&tb[128 * HW + 128], mm - 1);
    }
}

// ---------------------------------------------------------------------------
// K3: decode winners + nearest-sample + write 5 output planes; re-zero table.
//     ix = w_src & ~1, iy = h_src & ~1 (round-half-even collapse);
//     empty cell (0) decodes to (0,0) which is exactly correct.
// ---------------------------------------------------------------------------
__global__ void __launch_bounds__(256)
gather_kernel(const float* __restrict__ conf, const float* __restrict__ depth,
              float* __restrict__ out, int bs) {
    int blk = blockIdx.x;
    int b   = blk >> 6;
    int sub = blk & (BPB - 1);
    int tid = threadIdx.x;
    int p   = (sub << 10) + (tid << 2);

    bool emp = (__ldg(&g_flag[b]) == 0);
    int4* tp = reinterpret_cast<int4*>(g_table + b * HW2 + p);
    int4 k4 = *tp;
    *tp = make_int4(0, 0, 0, 0);           // restore zero state for next call
    int s[4] = {k4.x, k4.y, k4.z, k4.w};

    const float* db = depth + (size_t)b * HW2;
    const float* cb = conf  + (size_t)b * HW2;
    const unsigned* bb = g_bits + (b << 11);

    float4 ox, oy, od, oc, om;
    float *oxp = &ox.x, *oyp = &oy.x, *odp = &od.x, *ocp = &oc.x, *omp = &om.x;
    #pragma unroll
    for (int k = 0; k < 4; k++) {
        int ix = (s[k] & (HW - 1)) & ~1;
        int iy = ((s[k] >> 8) & (HW - 1)) & ~1;
        int cell = iy * HW + ix;
        float m = (emp || ((__ldg(&bb[cell >> 5]) >> (cell & 31)) & 1u)) ? 1.0f : 0.0f;
        float d = __ldg(db + cell);
        float c = __ldg(cb + cell);
        oxp[k] = ((float)ix * (1.0f / 280.0f)) * m;
        oyp[k] = ((float)iy * (1.0f / 280.0f)) * m;
        odp[k] = d * m;
        ocp[k] = c;
        omp[k] = m;
    }

    size_t o0 = (size_t)b * 3 * HW2 + p;
    __stcs(reinterpret_cast<float4*>(out + o0),           ox);
    __stcs(reinterpret_cast<float4*>(out + o0 + HW2),     oy);
    __stcs(reinterpret_cast<float4*>(out + o0 + 2 * HW2), od);
    __stcs(reinterpret_cast<float4*>(out + (size_t)bs * 3 * HW2 + (size_t)b * HW2 + p), oc);
    __stcs(reinterpret_cast<float4*>(out + (size_t)bs * 4 * HW2 + (size_t)b * HW2 + p), om);
}

// ---------------------------------------------------------------------------
extern "C" void kernel_launch(void* const* d_in, const int* in_sizes, int n_in,
                              void* d_out, int out_size) {
    const float* grid  = (const float*)d_in[0];
    const float* seg   = (const float*)d_in[1];
    const float* conf  = (const float*)d_in[2];
    const float* depth = (const float*)d_in[3];
    float* out = (float*)d_out;

    int bs = in_sizes[1] / HW2;   // 128

    count_kernel<<<bs * BPB, 256>>>(seg);
    scatter_kernel<<<bs * BPB, 256>>>(grid);
    gather_kernel<<<bs * BPB, 256>>>(conf, depth, out, bs);
}

// round 8
// speedup vs baseline: 2.6150x; 1.6507x over previous
#include <cuda_runtime.h>
#include <cuda_bf16.h>
#include <cstdint>

#define HW   256
#define HW2  65536
#define MAX_BS 128
#define BPB  64            // blocks per batch (256 thr * 4 px = 1024 px/block)

// Scratch (__device__ globals, zero at module load — no allocations).
// g_table is restored to all-zero by gather_kernel (read-then-clear) so no
// memset node is ever needed. g_flag is a plain deterministic store each call.
__device__ int      g_table[MAX_BS * HW2];        // winner p per cell, 0 = empty (aliases p=0, same decode)
__device__ unsigned g_bits[MAX_BS * (HW2 / 32)];  // seg>0.5 bitmask
__device__ int      g_flag[MAX_BS];               // 1 if any valid px (written by fixup)

// ---------------------------------------------------------------------------
// K1: pure scatter. Reads seg+grid, emits bitmask, RED.MAX for VALID px only.
//     No bookkeeping atomics, no block reductions, no syncs.
// ---------------------------------------------------------------------------
__global__ void __launch_bounds__(256)
scatter_kernel(const float* __restrict__ grid, const float* __restrict__ seg) {
    int blk = blockIdx.x;
    int b   = blk >> 6;                    // / BPB
    int sub = blk & (BPB - 1);
    int tid = threadIdx.x;
    int p   = (sub << 10) + (tid << 2);    // in-batch pixel index (4/thread)

    const float* segb = seg + (size_t)b * HW2;
    float4 s4 = __ldcs(reinterpret_cast<const float4*>(segb + p));
    bool v[4] = {s4.x > 0.5f, s4.y > 0.5f, s4.z > 0.5f, s4.w > 0.5f};

    // bitmask word (32 px = 8 threads * 4 bits), shuffle-OR assembly
    unsigned nib = (unsigned)v[0] | ((unsigned)v[1] << 1) |
                   ((unsigned)v[2] << 2) | ((unsigned)v[3] << 3);
    unsigned w = nib << ((tid & 7) << 2);
    w |= __shfl_xor_sync(0xffffffffu, w, 1);
    w |= __shfl_xor_sync(0xffffffffu, w, 2);
    w |= __shfl_xor_sync(0xffffffffu, w, 4);
    if ((tid & 7) == 0) g_bits[(b << 11) + (p >> 5)] = w;

    const float* gxb = grid + (size_t)b * 2 * HW2;
    float4 gx4 = __ldcs(reinterpret_cast<const float4*>(gxb + p));
    float4 gy4 = __ldcs(reinterpret_cast<const float4*>(gxb + HW2 + p));
    float gx[4] = {gx4.x, gx4.y, gx4.z, gx4.w};
    float gy[4] = {gy4.x, gy4.y, gy4.z, gy4.w};

    int* tb = g_table + b * HW2;
    #pragma unroll
    for (int k = 0; k < 4; k++) {
        if (v[k]) {
            int ix = (int)((gx[k] + 1.0f) * 0.5f * (float)HW);
            int iy = (int)((gy[k] + 1.0f) * 0.5f * (float)HW);
            ix = min(max(ix, 0), HW - 1);
            iy = min(max(iy, 0), HW - 1);
            atomicMax(&tb[iy * HW + ix], p + k);   // RED.MAX, no return
        }
    }
}

// ---------------------------------------------------------------------------
// K2: fixup, one block (256 thr) per batch. Scans seg top-down in 256-px
//     chunks; the first chunk containing an invalid pixel yields the GLOBAL
//     max-invalid index (top-down scan). Stops once both an invalid and a
//     valid pixel have been seen (expected: 1 chunk for random data).
//     Non-empty -> plant max-invalid winner at the hot (128,128) cell;
//     empty -> full unmasked scatter for this batch (rare slow path).
// ---------------------------------------------------------------------------
__global__ void __launch_bounds__(256)
fixup_kernel(const float* __restrict__ grid, const float* __restrict__ seg) {
    int b = blockIdx.x;
    int tid = threadIdx.x;
    const float* segb = seg + (size_t)b * HW2;
    __shared__ int s_valid, s_minv;
    if (tid == 0) { s_valid = 0; s_minv = -1; }
    __syncthreads();

    for (int base = HW2 - 256; base >= 0; base -= 256) {   // stride == blockDim
        int p = base + tid;
        float sv = segb[p];
        if (sv > 0.5f) s_valid = 1;
        else           atomicMax(&s_minv, p);       // smem atomic
        __syncthreads();
        if (s_valid && s_minv >= 0) break;          // uniform decision
        __syncthreads();
    }

    int* tb = g_table + b * HW2;
    if (s_valid) {
        if (tid == 0 && s_minv >= 0)
            atomicMax(&tb[128 * HW + 128], s_minv); // dedup hot cell: 1 atomic
    } else {
        // empty batch: reference scatters ALL pixels unmasked
        const float* gxb = grid + (size_t)b * 2 * HW2;
        #pragma unroll 1
        for (int i = 0; i < 64; i++) {
            int p = ((i << 8) + tid) << 2;
            float4 gx4 = *reinterpret_cast<const float4*>(gxb + p);
            float4 gy4 = *reinterpret_cast<const float4*>(gxb + HW2 + p);
            float gx[4] = {gx4.x, gx4.y, gx4.z, gx4.w};
            float gy[4] = {gy4.x, gy4.y, gy4.z, gy4.w};
            #pragma unroll
            for (int k = 0; k < 4; k++) {
                int ix = (int)((gx[k] + 1.0f) * 0.5f * (float)HW);
                int iy = (int)((gy[k] + 1.0f) * 0.5f * (float)HW);
                ix = min(max(ix, 0), HW - 1);
                iy = min(max(iy, 0), HW - 1);
                atomicMax(&tb[iy * HW + ix], p + k);
            }
        }
    }
    if (tid == 0) g_flag[b] = s_valid;              // deterministic store
}

// ---------------------------------------------------------------------------
// K3: decode winners + nearest-sample + write 5 output planes; re-zero table.
//     ix = w_src & ~1, iy = h_src & ~1 (round-half-even collapse);
//     untouched cell (0) decodes to (0,0) which is exactly correct.
// ---------------------------------------------------------------------------
__global__ void __launch_bounds__(256)
gather_kernel(const float* __restrict__ conf, const float* __restrict__ depth,
              float* __restrict__ out, int bs) {
    int blk = blockIdx.x;
    int b   = blk >> 6;
    int sub = blk & (BPB - 1);
    int tid = threadIdx.x;
    int p   = (sub << 10) + (tid << 2);

    bool emp = (__ldg(&g_flag[b]) == 0);
    int4* tp = reinterpret_cast<int4*>(g_table + b * HW2 + p);
    int4 k4 = *tp;
    *tp = make_int4(0, 0, 0, 0);           // restore zero state for next call
    int s[4] = {k4.x, k4.y, k4.z, k4.w};

    const float* db = depth + (size_t)b * HW2;
    const float* cb = conf  + (size_t)b * HW2;
    const unsigned* bb = g_bits + (b << 11);

    float4 ox, oy, od, oc, om;
    float *oxp = &ox.x, *oyp = &oy.x, *odp = &od.x, *ocp = &oc.x, *omp = &om.x;
    #pragma unroll
    for (int k = 0; k < 4; k++) {
        int ix = (s[k] & (HW - 1)) & ~1;
        int iy = ((s[k] >> 8) & (HW - 1)) & ~1;
        int cell = iy * HW + ix;
        float m = (emp || ((__ldg(&bb[cell >> 5]) >> (cell & 31)) & 1u)) ? 1.0f : 0.0f;
        float d = __ldg(db + cell);
        float c = __ldg(cb + cell);
        oxp[k] = ((float)ix * (1.0f / 280.0f)) * m;
        oyp[k] = ((float)iy * (1.0f / 280.0f)) * m;
        odp[k] = d * m;
        ocp[k] = c;
        omp[k] = m;
    }

    size_t o0 = (size_t)b * 3 * HW2 + p;
    __stcs(reinterpret_cast<float4*>(out + o0),           ox);
    __stcs(reinterpret_cast<float4*>(out + o0 + HW2),     oy);
    __stcs(reinterpret_cast<float4*>(out + o0 + 2 * HW2), od);
    __stcs(reinterpret_cast<float4*>(out + (size_t)bs * 3 * HW2 + (size_t)b * HW2 + p), oc);
    __stcs(reinterpret_cast<float4*>(out + (size_t)bs * 4 * HW2 + (size_t)b * HW2 + p), om);
}

// ---------------------------------------------------------------------------
extern "C" void kernel_launch(void* const* d_in, const int* in_sizes, int n_in,
                              void* d_out, int out_size) {
    const float* grid  = (const float*)d_in[0];
    const float* seg   = (const float*)d_in[1];
    const float* conf  = (const float*)d_in[2];
    const float* depth = (const float*)d_in[3];
    float* out = (float*)d_out;

    int bs = in_sizes[1] / HW2;   // 128

    scatter_kernel<<<bs * BPB, 256>>>(grid, seg);
    fixup_kernel<<<bs, 256>>>(grid, seg);
    gather_kernel<<<bs * BPB, 256>>>(conf, depth, out, bs);
}